// round 1
// baseline (speedup 1.0000x reference)
#include <cuda_runtime.h>

// ---------------------------------------------------------------------------
// Shapes (fixed by the problem): B=4, N=256, E=64, C=128, H=256.
// out[b,n,m] = W3 . relu(W2 . relu(W1 . concat(edge[b,:,n,m],
//                                              node[b,:,n], node[b,:,m]) + b1) + b2) + b3
//
// Factorization: W1 = [W1e(256x64) | W1r(256x128) | W1c(256x128)]
//   R[b,n,h] = W1r . node[b,:,n]
//   C[b,m,h] = W1c . node[b,:,m] + b1[h]
//   h1[b,n,m,h] = relu(W1e . edge[b,:,n,m] + R[b,n,h] + C[b,m,h])
// ---------------------------------------------------------------------------

__device__ float g_W1eT[64 * 256];     // [e][h]
__device__ float g_W1rT[128 * 256];    // [c][h]
__device__ float g_W1cT[128 * 256];    // [c][h]
__device__ float g_W2T[256 * 256];     // [k][h]
__device__ float g_R[4 * 256 * 256];   // [b][n][h]
__device__ float g_C[4 * 256 * 256];   // [b][m][h]  (b1 folded in)

// --- kernel 1: transpose weights into [k][h] layouts (coalesced consumers) ---
__global__ void prep_transpose(const float* __restrict__ W1,
                               const float* __restrict__ W2) {
    int i = blockIdx.x * 256 + threadIdx.x;   // grid 256 x 256 = 65536
    int k = i >> 8, h = i & 255;
    if (i < 64 * 256)  g_W1eT[i] = W1[h * 320 + k];
    if (i < 128 * 256) {
        g_W1rT[i] = W1[h * 320 + 64 + k];
        g_W1cT[i] = W1[h * 320 + 192 + k];
    }
    g_W2T[i] = W2[h * 256 + k];
}

// --- kernel 2: per-(b,p) node projections R and C ---
__global__ void prep_nodeproj(const float* __restrict__ node,
                              const float* __restrict__ b1) {
    int b = blockIdx.x >> 8, p = blockIdx.x & 255;   // 1024 blocks
    int h = threadIdx.x;                             // 256 threads
    __shared__ float ns[128];
    if (h < 128) ns[h] = node[(b * 128 + h) * 256 + p];
    __syncthreads();
    float r = 0.f, c = 0.f;
#pragma unroll 16
    for (int k = 0; k < 128; k++) {
        float v = ns[k];
        r = fmaf(g_W1rT[k * 256 + h], v, r);
        c = fmaf(g_W1cT[k * 256 + h], v, c);
    }
    int o = (b * 256 + p) * 256 + h;
    g_R[o] = r;
    g_C[o] = c + b1[h];
}

// --- kernel 3: fused per-pixel MLP ---------------------------------------
// Block tile: 64 m-pixels (fixed b, n) x 256 hidden channels.
// 256 threads, thread tile 8x8 (tm = tid&7 covers m, th = tid>>3 covers h).
// Dynamic smem layout (floats):
//   phase 1: Es[64][64] at 0, W1s[64][256] at 4096           (peak 20480)
//   phase 2: h1T[256][64] at 0, W2s[32][256] at 16384,
//            Rs[256] at 24576, red[32][64] reuses W2s region (peak 24832)
#define SMEM_FLOATS (256 * 64 + 32 * 256 + 256)

__global__ __launch_bounds__(256, 2)
void fused_mlp(const float* __restrict__ edge,
               const float* __restrict__ b2,
               const float* __restrict__ W3,
               const float* __restrict__ b3,
               float* __restrict__ out) {
    extern __shared__ float smem[];
    float* Es  = smem;                      // [64][64]
    float* W1s = smem + 64 * 64;            // [64][256]
    float* h1T = smem;                      // [256][64] (reuses Es/W1s)
    float* W2s = smem + 256 * 64;           // [32][256]
    float* Rs  = smem + 256 * 64 + 32 * 256;// [256]
    float* red = smem + 256 * 64;           // [32][64] (reuses W2s at the end)

    const int tid = threadIdx.x;
    const int tm = tid & 7, th = tid >> 3;
    const int mt = blockIdx.x, n = blockIdx.y, b = blockIdx.z;
    const int m0 = mt * 64;

    // load R row for this (b, n)
    if (tid < 64)
        ((float4*)Rs)[tid] = ((const float4*)(g_R + (b * 256 + n) * 256))[tid];

    // load edge tile Es[e][m]   (edge[b, e, n, m0 + m])
    const float* eb = edge + ((b * 64) * 256 + n) * 256 + m0;
#pragma unroll
    for (int r = 0; r < 4; r++) {
        int idx = r * 256 + tid;
        int e = idx >> 4, q = idx & 15;
        ((float4*)Es)[e * 16 + q] = *(const float4*)(eb + e * 65536 + q * 4);
    }
    // load W1e^T [64][256]
#pragma unroll
    for (int r = 0; r < 16; r++)
        ((float4*)W1s)[r * 256 + tid] = ((const float4*)g_W1eT)[r * 256 + tid];
    __syncthreads();

    // ---- phase 1: h1-preact = W1e . edge  (M=64, N=256, K=64) ----
    float acc[8][8];
#pragma unroll
    for (int i = 0; i < 8; i++)
#pragma unroll
        for (int j = 0; j < 8; j++) acc[i][j] = 0.f;

#pragma unroll 8
    for (int k = 0; k < 64; k++) {
        float a[8], w[8];
        *(float4*)(a)     = *(float4*)(Es + k * 64 + tm * 8);
        *(float4*)(a + 4) = *(float4*)(Es + k * 64 + tm * 8 + 4);
        *(float4*)(w)     = *(float4*)(W1s + k * 256 + th * 8);
        *(float4*)(w + 4) = *(float4*)(W1s + k * 256 + th * 8 + 4);
#pragma unroll
        for (int i = 0; i < 8; i++)
#pragma unroll
            for (int j = 0; j < 8; j++)
                acc[i][j] = fmaf(a[i], w[j], acc[i][j]);
    }

    // epilogue 1: relu(acc + R + C), C has b1 folded in
    float rj[8];
#pragma unroll
    for (int j = 0; j < 8; j++) rj[j] = Rs[th * 8 + j];
    const float* Cg = g_C + ((b * 256) + m0) * 256;
#pragma unroll
    for (int i = 0; i < 8; i++) {
        const float* cp = Cg + (tm * 8 + i) * 256 + th * 8;
        float4 c0 = *(const float4*)(cp);
        float4 c1 = *(const float4*)(cp + 4);
        float cv[8] = {c0.x, c0.y, c0.z, c0.w, c1.x, c1.y, c1.z, c1.w};
#pragma unroll
        for (int j = 0; j < 8; j++)
            acc[i][j] = fmaxf(acc[i][j] + rj[j] + cv[j], 0.f);
    }
    __syncthreads();   // done reading Es/W1s; safe to overwrite with h1T

    // store h1 transposed: h1T[h][m]
#pragma unroll
    for (int j = 0; j < 8; j++) {
        float4 p0 = make_float4(acc[0][j], acc[1][j], acc[2][j], acc[3][j]);
        float4 p1 = make_float4(acc[4][j], acc[5][j], acc[6][j], acc[7][j]);
        *(float4*)(h1T + (th * 8 + j) * 64 + tm * 8)     = p0;
        *(float4*)(h1T + (th * 8 + j) * 64 + tm * 8 + 4) = p1;
    }
    __syncthreads();

    // ---- phase 2: h2-preact = W2 . h1  (M=64, N=256, K=256) ----
    float acc2[8][8];
#pragma unroll
    for (int i = 0; i < 8; i++)
#pragma unroll
        for (int j = 0; j < 8; j++) acc2[i][j] = 0.f;

    for (int kc = 0; kc < 256; kc += 32) {
        // stage W2^T chunk [32][256]
        const float4* wsrc = (const float4*)(g_W2T + kc * 256);
#pragma unroll
        for (int r = 0; r < 8; r++)
            ((float4*)W2s)[r * 256 + tid] = wsrc[r * 256 + tid];
        __syncthreads();
#pragma unroll 8
        for (int k = 0; k < 32; k++) {
            float a[8], w[8];
            *(float4*)(a)     = *(float4*)(h1T + (kc + k) * 64 + tm * 8);
            *(float4*)(a + 4) = *(float4*)(h1T + (kc + k) * 64 + tm * 8 + 4);
            *(float4*)(w)     = *(float4*)(W2s + k * 256 + th * 8);
            *(float4*)(w + 4) = *(float4*)(W2s + k * 256 + th * 8 + 4);
#pragma unroll
            for (int i = 0; i < 8; i++)
#pragma unroll
                for (int j = 0; j < 8; j++)
                    acc2[i][j] = fmaf(a[i], w[j], acc2[i][j]);
        }
        __syncthreads();
    }

    // ---- epilogue 2 + layer 3: out[m] = b3 + sum_h W3[h] * relu(acc2 + b2) ----
    float po[8];
#pragma unroll
    for (int i = 0; i < 8; i++) po[i] = 0.f;
#pragma unroll
    for (int j = 0; j < 8; j++) {
        int h = th * 8 + j;
        float w3 = W3[h], bb = b2[h];
#pragma unroll
        for (int i = 0; i < 8; i++)
            po[i] = fmaf(w3, fmaxf(acc2[i][j] + bb, 0.f), po[i]);
    }
    // cross-thread reduction over th (32 groups of 8 h each)
#pragma unroll
    for (int i = 0; i < 8; i++)
        red[th * 64 + tm * 8 + i] = po[i];
    __syncthreads();
    if (tid < 64) {
        float s = b3[0];
#pragma unroll
        for (int t = 0; t < 32; t++) s += red[t * 64 + tid];
        out[(b * 256 + n) * 256 + m0 + tid] = s;
    }
}

extern "C" void kernel_launch(void* const* d_in, const int* in_sizes, int n_in,
                              void* d_out, int out_size) {
    const float* edge = (const float*)d_in[0];
    const float* node = (const float*)d_in[1];
    const float* W1   = (const float*)d_in[2];
    const float* b1   = (const float*)d_in[3];
    const float* W2   = (const float*)d_in[4];
    const float* b2   = (const float*)d_in[5];
    const float* W3   = (const float*)d_in[6];
    const float* b3   = (const float*)d_in[7];
    float* out = (float*)d_out;

    cudaFuncSetAttribute(fused_mlp, cudaFuncAttributeMaxDynamicSharedMemorySize,
                         SMEM_FLOATS * (int)sizeof(float));

    prep_transpose<<<256, 256>>>(W1, W2);
    prep_nodeproj<<<1024, 256>>>(node, b1);
    dim3 grid(4, 256, 4);   // (m-tile, n, b)
    fused_mlp<<<grid, 256, SMEM_FLOATS * sizeof(float)>>>(edge, b2, W3, b3, out);
}